// round 2
// baseline (speedup 1.0000x reference)
#include <cuda_runtime.h>
#include <cstdint>

// ---------------------------------------------------------------------------
// DoubleAttention, restructured:
//   L = [wB;wV] x + [bB;bV]            (GEMM, M=512 x2, N=4096, K=512, per batch)
//   Bm, av = softmax_rows(L)           (rows of length 4096)
//   S  = Bm @ x^T  * (1/4096)          (GEMM, M=512, N=512, K=4096)
//   gd = S @ wA^T + bA/4096            (GEMM, M=512, N=512, K=512)
//   out= gd^T @ av                     (GEMM, M=512, N=4096, K=512)
// The conv1x1(x,wA) tensor is algebraically eliminated (softmax rows sum to 1).
// All GEMMs run in tf32 (round-to-nearest) on tensor cores, fp32 accumulate.
// ---------------------------------------------------------------------------

#define BB   8
#define CC   512
#define HW_  4096

#define BM 128
#define BN 128
#define BK 16
#define PADA 8
#define PADB 8

// Scratch (no allocation allowed; __device__ globals are the sanctioned path)
__device__ float g_logits[(long)BB * 2 * CC * HW_];  // [8, 1024, 4096] = 134MB
__device__ float g_S [BB * CC * CC];                 // 8MB
__device__ float g_gd[BB * CC * CC];                 // 8MB

__device__ __forceinline__ uint32_t f2tf(float f) {
    uint32_t u;
    asm("cvt.rna.tf32.f32 %0, %1;" : "=r"(u) : "f"(f));
    return u;
}

__device__ __forceinline__ void mma8(float* c, const uint32_t* a, const uint32_t* b) {
    asm volatile(
        "mma.sync.aligned.m16n8k8.row.col.f32.tf32.tf32.f32 "
        "{%0,%1,%2,%3},{%4,%5,%6,%7},{%8,%9},{%0,%1,%2,%3};"
        : "+f"(c[0]), "+f"(c[1]), "+f"(c[2]), "+f"(c[3])
        : "r"(a[0]), "r"(a[1]), "r"(a[2]), "r"(a[3]), "r"(b[0]), "r"(b[1]));
}

// D[m,n] = scale * sum_k A[m,k]*B[k,n]  (+ biasScale*bias[m or n])
// TA: A stored as [K, M] row-major (i.e., A[k*M+m]); else [M, K].
// TB: B stored as [N, K] row-major (i.e., B[n*K+k]); else [K, N].
// blockIdx: x -> N tiles, y -> M tiles, z -> batch.
template <bool TA, bool TB>
__global__ __launch_bounds__(256, 1) void gemm_tf32(
    const float* __restrict__ Abase, const float* __restrict__ Bbase,
    float* __restrict__ Dbase, int M, int N, int K,
    long sA, long sB, long sD,
    const float* __restrict__ bias, int biasMode, float scale, float biasScale)
{
    __shared__ float As[2][BK][BM + PADA];
    __shared__ float Bs[2][BK][BN + PADB];

    const int bz = blockIdx.z;
    const float* A  = Abase + (long)bz * sA;
    const float* Bp = Bbase + (long)bz * sB;
    float* D        = Dbase + (long)bz * sD;

    const int bm   = blockIdx.y * BM;
    const int bn   = blockIdx.x * BN;
    const int tid  = threadIdx.x;
    const int lane = tid & 31;
    const int warp = tid >> 5;
    const int m0   = (warp >> 2) * 64;  // 2 warps along M
    const int n0   = (warp & 3) * 32;   // 4 warps along N
    const int r    = lane >> 2;         // 0..7
    const int cg   = lane & 3;          // 0..3

    float acc[4][4][4];
#pragma unroll
    for (int i = 0; i < 4; i++)
#pragma unroll
        for (int j = 0; j < 4; j++)
#pragma unroll
            for (int k = 0; k < 4; k++) acc[i][j][k] = 0.f;

    float4 pa[2], pb[2];

    auto loadA = [&](int k0) {
#pragma unroll
        for (int i = 0; i < 2; i++) {
            int idx = tid + i * 256;  // 512 float4 per tile
            if (!TA) {
                int m = idx >> 2, kq = idx & 3;
                pa[i] = *reinterpret_cast<const float4*>(&A[(long)(bm + m) * K + k0 + kq * 4]);
            } else {
                int k = idx >> 5, mq = idx & 31;
                pa[i] = *reinterpret_cast<const float4*>(&A[(long)(k0 + k) * M + bm + mq * 4]);
            }
        }
    };
    auto storeA = [&](int buf) {
#pragma unroll
        for (int i = 0; i < 2; i++) {
            int idx = tid + i * 256;
            if (!TA) {  // transpose into k-major smem
                int m = idx >> 2, kq = idx & 3;
                As[buf][kq * 4 + 0][m] = pa[i].x;
                As[buf][kq * 4 + 1][m] = pa[i].y;
                As[buf][kq * 4 + 2][m] = pa[i].z;
                As[buf][kq * 4 + 3][m] = pa[i].w;
            } else {
                int k = idx >> 5, mq = idx & 31;
                *reinterpret_cast<float4*>(&As[buf][k][mq * 4]) = pa[i];
            }
        }
    };
    auto loadB = [&](int k0) {
#pragma unroll
        for (int i = 0; i < 2; i++) {
            int idx = tid + i * 256;
            if (!TB) {
                int k = idx >> 5, nq = idx & 31;
                pb[i] = *reinterpret_cast<const float4*>(&Bp[(long)(k0 + k) * N + bn + nq * 4]);
            } else {
                int n = idx >> 2, kq = idx & 3;
                pb[i] = *reinterpret_cast<const float4*>(&Bp[(long)(bn + n) * K + k0 + kq * 4]);
            }
        }
    };
    auto storeB = [&](int buf) {
#pragma unroll
        for (int i = 0; i < 2; i++) {
            int idx = tid + i * 256;
            if (!TB) {
                int k = idx >> 5, nq = idx & 31;
                *reinterpret_cast<float4*>(&Bs[buf][k][nq * 4]) = pb[i];
            } else {  // transpose into k-major smem
                int n = idx >> 2, kq = idx & 3;
                Bs[buf][kq * 4 + 0][n] = pb[i].x;
                Bs[buf][kq * 4 + 1][n] = pb[i].y;
                Bs[buf][kq * 4 + 2][n] = pb[i].z;
                Bs[buf][kq * 4 + 3][n] = pb[i].w;
            }
        }
    };

    const int nk = K / BK;
    loadA(0); loadB(0);
    storeA(0); storeB(0);
    __syncthreads();

    for (int kt = 0; kt < nk; ++kt) {
        const int cur = kt & 1;
        const bool more = (kt + 1 < nk);
        if (more) { loadA((kt + 1) * BK); loadB((kt + 1) * BK); }

#pragma unroll
        for (int kk = 0; kk < BK; kk += 8) {
            uint32_t afr[4][4], bfr[4][2];
#pragma unroll
            for (int mt = 0; mt < 4; mt++) {
                int mrow = m0 + mt * 16;
                afr[mt][0] = f2tf(As[cur][kk + cg    ][mrow + r]);
                afr[mt][1] = f2tf(As[cur][kk + cg    ][mrow + r + 8]);
                afr[mt][2] = f2tf(As[cur][kk + cg + 4][mrow + r]);
                afr[mt][3] = f2tf(As[cur][kk + cg + 4][mrow + r + 8]);
            }
#pragma unroll
            for (int nt = 0; nt < 4; nt++) {
                int ncol = n0 + nt * 8 + r;
                bfr[nt][0] = f2tf(Bs[cur][kk + cg    ][ncol]);
                bfr[nt][1] = f2tf(Bs[cur][kk + cg + 4][ncol]);
            }
#pragma unroll
            for (int mt = 0; mt < 4; mt++)
#pragma unroll
                for (int nt = 0; nt < 4; nt++) mma8(acc[mt][nt], afr[mt], bfr[nt]);
        }

        if (more) {
            storeA(cur ^ 1); storeB(cur ^ 1);
            __syncthreads();
        }
    }

    // epilogue
#pragma unroll
    for (int mt = 0; mt < 4; mt++) {
        int row0 = bm + m0 + mt * 16 + r;
#pragma unroll
        for (int nt = 0; nt < 4; nt++) {
            int col = bn + n0 + nt * 8 + cg * 2;
            float v0 = acc[mt][nt][0] * scale;
            float v1 = acc[mt][nt][1] * scale;
            float v2 = acc[mt][nt][2] * scale;
            float v3 = acc[mt][nt][3] * scale;
            if (biasMode == 1) {
                float b0 = bias[row0] * biasScale;
                float b1 = bias[row0 + 8] * biasScale;
                v0 += b0; v1 += b0; v2 += b1; v3 += b1;
            } else if (biasMode == 2) {
                float b0 = bias[col] * biasScale;
                float b1 = bias[col + 1] * biasScale;
                v0 += b0; v1 += b1; v2 += b0; v3 += b1;
            }
            D[(long)row0 * N + col]           = v0;
            D[(long)row0 * N + col + 1]       = v1;
            D[(long)(row0 + 8) * N + col]     = v2;
            D[(long)(row0 + 8) * N + col + 1] = v3;
        }
    }
}

// In-place softmax over rows of length 4096. One CTA (256 threads) per row.
__global__ __launch_bounds__(256, 1) void softmax_rows(float* __restrict__ buf) {
    float* p = buf + (long)blockIdx.x * HW_;
    const int tid  = threadIdx.x;
    const int lane = tid & 31;
    const int warp = tid >> 5;
    __shared__ float red[8];

    float4 v[4];
    float4* p4 = reinterpret_cast<float4*>(p);
#pragma unroll
    for (int i = 0; i < 4; i++) v[i] = p4[i * 256 + tid];

    float mx = v[0].x;
#pragma unroll
    for (int i = 0; i < 4; i++) {
        mx = fmaxf(mx, v[i].x); mx = fmaxf(mx, v[i].y);
        mx = fmaxf(mx, v[i].z); mx = fmaxf(mx, v[i].w);
    }
#pragma unroll
    for (int o = 16; o; o >>= 1) mx = fmaxf(mx, __shfl_xor_sync(0xffffffffu, mx, o));
    if (lane == 0) red[warp] = mx;
    __syncthreads();
    mx = red[0];
#pragma unroll
    for (int w = 1; w < 8; w++) mx = fmaxf(mx, red[w]);
    __syncthreads();

    float s = 0.f;
#pragma unroll
    for (int i = 0; i < 4; i++) {
        v[i].x = __expf(v[i].x - mx); s += v[i].x;
        v[i].y = __expf(v[i].y - mx); s += v[i].y;
        v[i].z = __expf(v[i].z - mx); s += v[i].z;
        v[i].w = __expf(v[i].w - mx); s += v[i].w;
    }
#pragma unroll
    for (int o = 16; o; o >>= 1) s += __shfl_xor_sync(0xffffffffu, s, o);
    if (lane == 0) red[warp] = s;
    __syncthreads();
    s = 0.f;
#pragma unroll
    for (int w = 0; w < 8; w++) s += red[w];
    const float inv = 1.f / s;
#pragma unroll
    for (int i = 0; i < 4; i++) {
        v[i].x *= inv; v[i].y *= inv; v[i].z *= inv; v[i].w *= inv;
        p4[i * 256 + tid] = v[i];
    }
}

extern "C" void kernel_launch(void* const* d_in, const int* in_sizes, int n_in,
                              void* d_out, int out_size) {
    const float* x  = (const float*)d_in[0];
    const float* wA = (const float*)d_in[1];
    const float* bA = (const float*)d_in[2];
    const float* wB = (const float*)d_in[3];
    const float* bB = (const float*)d_in[4];
    const float* wV = (const float*)d_in[5];
    const float* bV = (const float*)d_in[6];
    float* out = (float*)d_out;

    float *logits, *S, *gd;
    cudaGetSymbolAddress((void**)&logits, g_logits);
    cudaGetSymbolAddress((void**)&S, g_S);
    cudaGetSymbolAddress((void**)&gd, g_gd);

    const long sX  = (long)CC * HW_;        // x batch stride
    const long sL  = (long)2 * CC * HW_;    // logits batch stride
    const long sCC = (long)CC * CC;
    const float invHW = 1.0f / (float)HW_;
    dim3 blk(256);

    // 1) B logits: wB[512,512] @ x[b][512,4096] + bB  -> logits[b, 0:512, :]
    gemm_tf32<false, false><<<dim3(HW_ / BN, CC / BM, BB), blk>>>(
        wB, x, logits, CC, HW_, CC, 0, sX, sL, bB, 1, 1.f, 1.f);
    // 2) V logits -> logits[b, 512:1024, :]
    gemm_tf32<false, false><<<dim3(HW_ / BN, CC / BM, BB), blk>>>(
        wV, x, logits + (long)CC * HW_, CC, HW_, CC, 0, sX, sL, bV, 1, 1.f, 1.f);
    // 3) softmax over all 8*1024 rows (Bm and av), in place
    softmax_rows<<<BB * 2 * CC, blk>>>(logits);
    // 4) S = (1/HW) * Bm @ x^T   (A=Bm [512,4096], B[n,k]=x[n*4096+k] -> TB)
    gemm_tf32<false, true><<<dim3(CC / BN, CC / BM, BB), blk>>>(
        logits, x, S, CC, CC, HW_, sL, sX, sCC, nullptr, 0, invHW, 1.f);
    // 5) gd = S @ wA^T + bA/HW   (B[n,k]=wA[n*512+k] -> TB; bias by n)
    gemm_tf32<false, true><<<dim3(CC / BN, CC / BM, BB), blk>>>(
        S, wA, gd, CC, CC, CC, sCC, 0, sCC, bA, 2, 1.f, invHW);
    // 6) out = gd^T @ av         (A[k,m]=gd[k*512+m] -> TA; B=av direct)
    gemm_tf32<true, false><<<dim3(HW_ / BN, CC / BM, BB), blk>>>(
        gd, logits + (long)CC * HW_, out, CC, HW_, CC, sCC, sL, (long)CC * HW_,
        nullptr, 0, 1.f, 1.f);
}